// round 11
// baseline (speedup 1.0000x reference)
#include <cuda_runtime.h>
#include <cuda_bf16.h>

#define BB 64
#define TT 1024
#define DD 64
#define HH 4
#define SPLIT 8
#define RPC 128
#define STRIDE 68
#define NEGF (-4294967296.0f)

// ---------------- shared smem layout (floats), 42128 bytes ----------------
#define OFF_KS   0                // A: key tile 128x68 = 8704 ; helper: W_Q[0,4096)+W_K stride68 [4096,8448)
#define OFF_P4   8704             // 512  (A: p per row, 4 heads)
#define OFF_ACC  9216             // 1024 (A: reduce scratch ; helper: part/q0/Qh/m/l/f/sc/qm)
#define OFF_U    10240            // 256  (A: u planar [h][d] ; helper: s_sm)
#define OFF_WRED 10496            // 32
#define OFF_MH   10528            // 4
#define SM_FLOATS 10532
#define SM_BYTES (SM_FLOATS * 4)

// A-CTA FFN overlay inside dead key tile (float offsets from OFF_KS)
#define FO_FW1   0                // 2048  fw1 col slice [64][32]
#define FO_FW2   2048             // 2048  fw2 row slice [32][64]
#define FO_FB1   4096             // 32
#define FO_FB2   4128             // 64
#define FO_RES   4192             // 64
#define FO_HID   4256             // 32

// helper offsets (floats)
#define HO_WQ    0                // 4096 (later W_V)
#define HO_WK    4096             // 64*68 = 4352
#define HO_PART  9216             // 256
#define HO_Q0    9472             // 64
#define HO_QH    9536             // 64
#define HO_MS    9600             // 32
#define HO_LS    9632             // 32
#define HO_FS    9664             // 32
#define HO_SC    9696             // 4
#define HO_QM    9700             // 1
#define HO_SSM   10240            // 256 (= OFF_U)

#define CP_ASYNC16(dst_u32, src) \
    asm volatile("cp.async.cg.shared.global [%0], [%1], 16;" :: "r"(dst_u32), "l"(src) : "memory")
#define CP_COMMIT() asm volatile("cp.async.commit_group;" ::: "memory")
#define CP_WAIT_GROUP(n) asm volatile("cp.async.wait_group %0;" :: "n"(n) : "memory")

// cross-CTA scratch + monotonic counters (replay-safe)
__device__ float    g_u[BB * 256];                   // [b][h*64+d]
__device__ float    g_pacc[BB * SPLIT * HH * DD];    // [b][s][h*64+d]
__device__ float    g_pm[BB * SPLIT * HH];
__device__ float    g_pl[BB * SPLIT * HH];
__device__ float    g_res[BB * DD];
__device__ unsigned g_epochU[BB], g_arriveU[BB];
__device__ unsigned g_doneP[BB],  g_arriveH[BB];
__device__ unsigned g_epochR[BB], g_arriveR[BB];

__global__ __launch_bounds__(256, 4)
void fused_transformer_kernel(
    const float* __restrict__ queries, const float* __restrict__ keys,
    const int* __restrict__ query_mask, const int* __restrict__ key_mask,
    const float* __restrict__ W_Q, const float* __restrict__ W_K,
    const float* __restrict__ W_V,
    const float* __restrict__ fw1, const float* __restrict__ fw2,
    const float* __restrict__ fb1, const float* __restrict__ fb2,
    float* __restrict__ out)
{
    extern __shared__ float sm[];
    const unsigned sbase = (unsigned)__cvta_generic_to_shared(sm);
    const int split = blockIdx.x;     // 0..7 = A ; 8 = helper
    const int b     = blockIdx.y;
    const int t     = threadIdx.x;
    __shared__ unsigned s_flag;

    // ======================= HELPER CTA =======================
    if (split == SPLIT) {
        float* wq_s  = sm + HO_WQ;
        float* wk_s  = sm + HO_WK;
        float* wv_s  = sm + HO_WQ;     // overlays W_Q after Qh
        float* part  = sm + HO_PART;
        float* q0    = sm + HO_Q0;
        float* Qh    = sm + HO_QH;
        float* m_s   = sm + HO_MS;
        float* l_s   = sm + HO_LS;
        float* f_s   = sm + HO_FS;
        float* sc_s  = sm + HO_SC;
        float* s_sm  = sm + HO_SSM;

        // stage W_Q (plain) + W_K (stride-68) via cp.async
        {
            const float4* gq = (const float4*)W_Q;
            const float4* gk = (const float4*)W_K;
            #pragma unroll
            for (int i = 0; i < 4; i++) {
                int idx = t + i * 256;
                CP_ASYNC16(sbase + (HO_WQ + idx * 4) * 4, gq + idx);
            }
            #pragma unroll
            for (int i = 0; i < 4; i++) {
                int idx = t + i * 256;
                int row = idx >> 4, c = idx & 15;
                CP_ASYNC16(sbase + (HO_WK + row * STRIDE + c * 4) * 4, gk + idx);
            }
            CP_COMMIT();
        }
        if (t < 16) ((float4*)q0)[t] = ((const float4*)(queries + (size_t)b * TT * DD))[t];
        if (t == 16) sm[HO_QM] = (float)query_mask[b * TT];
        CP_WAIT_GROUP(0);
        __syncthreads();

        // Qh = q0 @ W_Q
        {
            int j = t & 63, q = t >> 6;
            float a = 0.f;
            #pragma unroll
            for (int i = q * 16; i < q * 16 + 16; i++) a += q0[i] * wq_s[i * 64 + j];
            part[t] = a;
        }
        __syncthreads();
        if (t < 64) Qh[t] = part[t] + part[64 + t] + part[128 + t] + part[192 + t];
        __syncthreads();

        // W_V DMA into dead W_Q area
        {
            const float4* gv = (const float4*)W_V;
            #pragma unroll
            for (int i = 0; i < 4; i++) {
                int idx = t + i * 256;
                CP_ASYNC16(sbase + (HO_WQ + idx * 4) * 4, gv + idx);
            }
            CP_COMMIT();
        }

        // u[h*64+d] = 0.25 * W_K[d][h-blk] . Qh[h-blk] ; publish
        {
            int d = t & 63, h = t >> 6;
            const float4* wr  = (const float4*)(wk_s + d * STRIDE + h * 16);
            const float4* qh4 = (const float4*)(Qh + h * 16);
            float s = 0.f;
            #pragma unroll
            for (int c = 0; c < 4; c++) {
                float4 w = wr[c]; float4 q = qh4[c];
                s += w.x * q.x + w.y * q.y + w.z * q.z + w.w * q.w;
            }
            g_u[b * 256 + h * 64 + d] = s * 0.25f;
        }
        __syncthreads();
        if (t == 0) { __threadfence(); atomicAdd(&g_epochU[b], 1u); }

        // join: wait all 8 pacc publications for this replay
        if (t == 0) {
            unsigned old = atomicAdd(&g_arriveH[b], 1u);
            unsigned target = (old + 1u) * SPLIT;
            while (*(volatile unsigned*)&g_doneP[b] < target) __nanosleep(32);
            __threadfence();
            s_flag = 1u;
        }
        __syncthreads();

        if (t < 32) { m_s[t] = g_pm[b * 32 + t]; l_s[t] = g_pl[b * 32 + t]; }
        __syncthreads();

        // softmax split combine (warp 0; lane = s*4+h)
        if (t < 32) {
            float m = m_s[t], lv = l_s[t];
            float M = m;
            M = fmaxf(M, __shfl_xor_sync(0xffffffffu, M, 4));
            M = fmaxf(M, __shfl_xor_sync(0xffffffffu, M, 8));
            M = fmaxf(M, __shfl_xor_sync(0xffffffffu, M, 16));
            float f = __expf(m - M);
            f_s[t] = f;
            float L = lv * f;
            L += __shfl_xor_sync(0xffffffffu, L, 4);
            L += __shfl_xor_sync(0xffffffffu, L, 8);
            L += __shfl_xor_sync(0xffffffffu, L, 16);
            if (t < 4) sc_s[t] = sm[HO_QM] / L;
        }
        __syncthreads();

        // s_sm[h*64+d]
        {
            int d = t & 63, h = t >> 6;
            float S = 0.f;
            #pragma unroll
            for (int s = 0; s < SPLIT; s++)
                S += g_pacc[b * 2048 + s * 256 + h * 64 + d] * f_s[s * HH + h];
            s_sm[h * 64 + d] = S * sc_s[h];
        }
        CP_WAIT_GROUP(0);
        __syncthreads();

        // res[j] = s_sm[h(j)] @ W_V[:,j] + q0[j] ; publish
        {
            int j = t & 63, q = t >> 6;
            int h = j >> 4;
            float a = 0.f;
            #pragma unroll
            for (int d = q * 16; d < q * 16 + 16; d++) a += s_sm[h * 64 + d] * wv_s[d * 64 + j];
            part[t] = a;
        }
        __syncthreads();
        if (t < 64)
            g_res[b * 64 + t] = part[t] + part[64 + t] + part[128 + t] + part[192 + t] + q0[t];
        __syncthreads();
        if (t == 0) { __threadfence(); atomicAdd(&g_epochR[b], 1u); }
        return;
    }

    // ======================= A CTA (split 0..7) =======================
    float*  ks   = sm + OFF_KS;
    float4* p4   = (float4*)(sm + OFF_P4);
    float*  accf = sm + OFF_ACC;
    float*  u_s  = sm + OFF_U;
    float*  wred = sm + OFF_WRED;
    float*  mh   = sm + OFF_MH;

    const int k0   = split * RPC;
    const int lane = t & 31;
    const int wid  = t >> 5;

    if (split == 0 && t < 64) out[b * 64 + t] = 0.f;   // reset accumulator (ordered before doneP)

    // key tile DMA
    {
        const float4* kg = (const float4*)(keys + ((size_t)b * TT + k0) * DD);
        #pragma unroll
        for (int i = 0; i < 8; i++) {
            int idx = t + i * 256;
            int row = idx >> 4, c = idx & 15;
            CP_ASYNC16(sbase + (row * STRIDE + c * 4) * 4, kg + idx);
        }
        CP_COMMIT();
    }
    const int r = t & 127;         // key row for scores
    const int hp = t >> 7;         // head pair 0/1
    const int kmv = key_mask[b * TT + k0 + r];

    // spin for u (replay-indexed)
    if (t == 0) {
        unsigned old = atomicAdd(&g_arriveU[b], 1u);
        unsigned rr = old / SPLIT;
        while (*(volatile unsigned*)&g_epochU[b] < rr + 1u) __nanosleep(32);
        __threadfence();
        s_flag = 1u;
    }
    __syncthreads();
    if (t < 64) ((float4*)u_s)[t] = ((const float4*)(g_u + b * 256))[t];
    CP_WAIT_GROUP(0);
    __syncthreads();

    // scores: all 256 threads; thread = (row r, 2 heads 2hp,2hp+1)
    float s0, s1;
    {
        const float4* krow = (const float4*)&ks[r * STRIDE];
        const float4* uh0 = (const float4*)(u_s + (2 * hp) * 64);
        const float4* uh1 = uh0 + 16;
        float a0 = 0.f, a1 = 0.f;
        #pragma unroll
        for (int c = 0; c < 16; c++) {
            float4 kv = krow[c];
            float4 ua = uh0[c], ub = uh1[c];
            a0 += kv.x * ua.x + kv.y * ua.y + kv.z * ua.z + kv.w * ua.w;
            a1 += kv.x * ub.x + kv.y * ub.y + kv.z * ub.z + kv.w * ub.w;
        }
        bool masked = (kmv != 1) || ((k0 + r) == 0);
        s0 = masked ? NEGF : a0;
        s1 = masked ? NEGF : a1;
    }
    // warp max (each warp: 32 rows, 2 heads)
    {
        float m0 = s0, m1 = s1;
        #pragma unroll
        for (int o = 16; o; o >>= 1) {
            m0 = fmaxf(m0, __shfl_xor_sync(0xffffffffu, m0, o));
            m1 = fmaxf(m1, __shfl_xor_sync(0xffffffffu, m1, o));
        }
        if (lane == 0) { wred[wid * 2] = m0; wred[wid * 2 + 1] = m1; }
    }
    __syncthreads();
    if (t < 4) {
        int base = (t < 2) ? 0 : 8;        // heads 0,1 in warps 0-3 ; heads 2,3 in warps 4-7
        int col = (t < 2) ? t : (t - 2);
        float m = wred[base + col];
        #pragma unroll
        for (int w = 1; w < 4; w++) m = fmaxf(m, wred[base + w * 2 + col]);
        mh[t] = m;
    }
    __syncthreads();

    // p = exp(s - m); store packed halves; warp sums
    {
        float p0 = __expf(s0 - mh[2 * hp]);
        float p1 = __expf(s1 - mh[2 * hp + 1]);
        ((float2*)&p4[r])[hp] = make_float2(p0, p1);
        float l0 = p0, l1 = p1;
        #pragma unroll
        for (int o = 16; o; o >>= 1) {
            l0 += __shfl_xor_sync(0xffffffffu, l0, o);
            l1 += __shfl_xor_sync(0xffffffffu, l1, o);
        }
        if (lane == 0) { wred[wid * 2] = l0; wred[wid * 2 + 1] = l1; }
    }
    __syncthreads();
    if (t < 4) {
        int base = (t < 2) ? 0 : 8;
        int col = (t < 2) ? t : (t - 2);
        float l = wred[base + col];
        #pragma unroll
        for (int w = 1; w < 4; w++) l += wred[base + w * 2 + col];
        g_pm[(b * SPLIT + split) * HH + t] = mh[t];
        g_pl[(b * SPLIT + split) * HH + t] = l;
    }

    // weighted key sum: thread (d = t&63, quarter q) over 32 rows
    {
        int d = t & 63, q = t >> 6;
        float ax = 0.f, ay = 0.f, az = 0.f, aw = 0.f;
        const int kb = q * 32;
        #pragma unroll 4
        for (int kk = 0; kk < 32; kk++) {
            float kv = ks[(kb + kk) * STRIDE + d];
            float4 p = p4[kb + kk];
            ax += p.x * kv; ay += p.y * kv; az += p.z * kv; aw += p.w * kv;
        }
        ((float4*)accf)[t] = make_float4(ax, ay, az, aw);
    }
    __syncthreads();
    if (t < 64) {
        float4* am = (float4*)accf;
        float4 a = am[t], c = am[64 + t], d4 = am[128 + t], e = am[192 + t];
        float* gp = g_pacc + (b * SPLIT + split) * 256;
        gp[0 * 64 + t] = a.x + c.x + d4.x + e.x;
        gp[1 * 64 + t] = a.y + c.y + d4.y + e.y;
        gp[2 * 64 + t] = a.z + c.z + d4.z + e.z;
        gp[3 * 64 + t] = a.w + c.w + d4.w + e.w;
    }
    __syncthreads();
    if (t == 0) { __threadfence(); atomicAdd(&g_doneP[b], 1u); }

    // ---- FFN slice prefetch into dead key tile ----
    {
        const float4* g1 = (const float4*)fw1;                  // row stride = 64 f4
        const float4* g2 = (const float4*)(fw2 + split * 32 * 64);
        #pragma unroll
        for (int i = 0; i < 2; i++) {
            int idx = t + i * 256;
            int row = idx >> 3, c = idx & 7;
            CP_ASYNC16(sbase + (FO_FW1 + idx * 4) * 4, g1 + row * 64 + split * 8 + c);
        }
        #pragma unroll
        for (int i = 0; i < 2; i++) {
            int idx = t + i * 256;
            CP_ASYNC16(sbase + (FO_FW2 + idx * 4) * 4, g2 + idx);
        }
        if (t < 8) {
            CP_ASYNC16(sbase + (FO_FB1 + t * 4) * 4, ((const float4*)(fb1 + split * 32)) + t);
        } else if (t < 24) {
            CP_ASYNC16(sbase + (FO_FB2 + (t - 8) * 4) * 4, ((const float4*)fb2) + (t - 8));
        }
        CP_COMMIT();
    }

    // spin for res
    if (t == 0) {
        unsigned old = atomicAdd(&g_arriveR[b], 1u);
        unsigned rr = old / SPLIT;
        while (*(volatile unsigned*)&g_epochR[b] < rr + 1u) __nanosleep(32);
        __threadfence();
        s_flag = 2u;
    }
    __syncthreads();
    if (t < 16) ((float4*)(sm + FO_RES))[t] = ((const float4*)(g_res + b * 64))[t];
    CP_WAIT_GROUP(0);
    __syncthreads();

    float* fw1s = sm + FO_FW1;
    float* fw2s = sm + FO_FW2;
    float* res_s = sm + FO_RES;
    float* hid_s = sm + FO_HID;

    // hidden slice (32 units): thread (m = t&31, jq = t>>5) -> 8 j each
    {
        int m = t & 31, jq = t >> 5;
        float a = 0.f;
        #pragma unroll
        for (int j = jq * 8; j < jq * 8 + 8; j++) a += res_s[j] * fw1s[j * 32 + m];
        accf[jq * 32 + m] = a;
    }
    __syncthreads();
    if (t < 32) {
        float a = sm[FO_FB1 + t];
        #pragma unroll
        for (int w = 0; w < 8; w++) a += accf[w * 32 + t];
        hid_s[t] = (a > 0.f) ? a : 0.2f * a;
    }
    __syncthreads();

    // output partial
    {
        int j = t & 63, mq = t >> 6;
        float a = 0.f;
        #pragma unroll
        for (int m2 = mq * 8; m2 < mq * 8 + 8; m2++) a += hid_s[m2] * fw2s[m2 * 64 + j];
        accf[t] = a;
    }
    __syncthreads();
    if (t < 64) {
        float v = accf[t] + accf[64 + t] + accf[128 + t] + accf[192 + t];
        if (split == 0) v += res_s[t] + sm[FO_FB2 + t];
        atomicAdd(&out[b * 64 + t], v);
    }
}

extern "C" void kernel_launch(void* const* d_in, const int* in_sizes, int n_in,
                              void* d_out, int out_size)
{
    const float* queries = (const float*)d_in[0];
    const float* keys    = (const float*)d_in[1];
    const int*   qmask   = (const int*)d_in[2];
    const int*   kmask   = (const int*)d_in[3];
    const float* W_Q     = (const float*)d_in[4];
    const float* W_K     = (const float*)d_in[5];
    const float* W_V     = (const float*)d_in[6];
    const float* fw1     = (const float*)d_in[7];
    const float* fw2     = (const float*)d_in[8];
    const float* fb1     = (const float*)d_in[9];
    const float* fb2     = (const float*)d_in[10];
    float* out = (float*)d_out;

    cudaFuncSetAttribute(fused_transformer_kernel,
                         cudaFuncAttributeMaxDynamicSharedMemorySize, SM_BYTES);

    fused_transformer_kernel<<<dim3(SPLIT + 1, BB), 256, SM_BYTES>>>(
        queries, keys, qmask, kmask, W_Q, W_K, W_V, fw1, fw2, fb1, fb2, out);
}

// round 12
// speedup vs baseline: 1.2074x; 1.2074x over previous
#include <cuda_runtime.h>
#include <cuda_bf16.h>

#define BB 64
#define TT 1024
#define DD 64
#define HH 4
#define NRANK 4
#define RPC 256
#define STRIDE 68
#define NEGF (-4294967296.0f)

// ---------------- smem layout (floats) ----------------
#define OFF_KS   0          // key tile 256x68 = 17408 (FFN overlay later)
#define OFF_P4   17408      // 1024 (p per row, 4 heads)
#define OFF_ACC  18432      // 1024 (reduce scratch; later s_sm[256]+part[256])
#define OFF_U    19456      // 256  (u[d*4+h])
#define OFF_Q0   19712      // 64
#define OFF_QH   19776      // 64
#define OFF_WRED 19840      // 64
#define OFF_MH   19904      // 4
#define OFF_MS   19908      // 16
#define OFF_LS   19924      // 16
#define OFF_FS   19940      // 16
#define OFF_SC   19956      // 4
#define OFF_QM   19960      // 4 (padded)
#define SM_FLOATS 19964
#define SM_BYTES (SM_FLOATS * 4)

// FFN overlay inside dead key tile (float offsets from OFF_KS)
#define FO_FW1   0          // 4096: fw1 col-slice [64 j][64 m]
#define FO_FW2   4096       // 4096: fw2 row-slice [64 m][64 j]
#define FO_FB1   8192       // 64
#define FO_FB2   8256       // 64
#define FO_RES   8320       // 64
#define FO_HID   8384       // 64

#define CP_ASYNC16(dst_u32, src) \
    asm volatile("cp.async.cg.shared.global [%0], [%1], 16;" :: "r"(dst_u32), "l"(src) : "memory")
#define CP_COMMIT() asm volatile("cp.async.commit_group;" ::: "memory")
#define CP_WAIT_GROUP(n) asm volatile("cp.async.wait_group %0;" :: "n"(n) : "memory")

// cross-CTA exchange (written+read within one replay, ordered by cluster barrier)
__device__ float g_pacc[BB * NRANK * HH * DD];   // [b][r][h*64+d]
__device__ float g_pm[BB * NRANK * HH];          // [b][r*4+h]
__device__ float g_pl[BB * NRANK * HH];

__global__ __launch_bounds__(256, 2) __cluster_dims__(NRANK, 1, 1)
void fused_transformer_kernel(
    const float* __restrict__ queries, const float* __restrict__ keys,
    const int* __restrict__ query_mask, const int* __restrict__ key_mask,
    const float* __restrict__ W_Q, const float* __restrict__ W_K,
    const float* __restrict__ W_V,
    const float* __restrict__ fw1, const float* __restrict__ fw2,
    const float* __restrict__ fb1, const float* __restrict__ fb2,
    float* __restrict__ out)
{
    extern __shared__ float sm[];
    const unsigned sbase = (unsigned)__cvta_generic_to_shared(sm);

    float*  ks   = sm + OFF_KS;
    float4* p4   = (float4*)(sm + OFF_P4);
    float*  accf = sm + OFF_ACC;
    float*  u    = sm + OFF_U;
    float*  q0   = sm + OFF_Q0;
    float*  Qh   = sm + OFF_QH;
    float*  wred = sm + OFF_WRED;
    float*  mh   = sm + OFF_MH;
    float*  m_s  = sm + OFF_MS;
    float*  l_s  = sm + OFF_LS;
    float*  f_s  = sm + OFF_FS;
    float*  sc_s = sm + OFF_SC;

    const int r    = blockIdx.x;          // cluster rank 0..3
    const int b    = blockIdx.y;
    const int t    = threadIdx.x;
    const int k0   = r * RPC;
    const int lane = t & 31;
    const int wid  = t >> 5;

    // rank 0 zeroes the output accumulator (ordered before atomicAdds via cluster barrier)
    if (r == 0 && t < 64) out[b * 64 + t] = 0.f;

    // ---- key tile DMA: 256 rows x 16 f4 = 4096 f4, 16 per thread ----
    {
        const float4* kg = (const float4*)(keys + ((size_t)b * TT + k0) * DD);
        #pragma unroll
        for (int i = 0; i < 16; i++) {
            int idx = t + i * 256;
            int row = idx >> 4, c = idx & 15;
            CP_ASYNC16(sbase + (row * STRIDE + c * 4) * 4, kg + idx);
        }
        CP_COMMIT();
    }
    const int kmv = key_mask[b * TT + k0 + t];
    if (t < 16) ((float4*)q0)[t] = ((const float4*)(queries + (size_t)b * TT * DD))[t];
    if (t == 64) sm[OFF_QM] = (float)query_mask[b * TT];
    __syncthreads();

    // ---- u computed redundantly per CTA (weights are L2-broadcast) ----
    // Qh partial: thread (j, quarter), MLP 16
    {
        int j = t & 63, q = t >> 6;
        float a = 0.f;
        #pragma unroll
        for (int i = q * 16; i < q * 16 + 16; i++) a += q0[i] * W_Q[i * 64 + j];
        accf[t] = a;
    }
    __syncthreads();
    if (t < 64) Qh[t] = accf[t] + accf[64 + t] + accf[128 + t] + accf[192 + t];
    __syncthreads();
    // u[d*4+h] = 0.25 * W_K[d][h-blk] . Qh[h-blk]
    {
        int d = t & 63, h = t >> 6;
        const float4* wr  = (const float4*)(W_K + d * 64 + h * 16);
        const float4* qh4 = (const float4*)(Qh + h * 16);
        float s = 0.f;
        #pragma unroll
        for (int c = 0; c < 4; c++) {
            float4 w = wr[c]; float4 q = qh4[c];
            s += w.x * q.x + w.y * q.y + w.z * q.z + w.w * q.w;
        }
        u[d * 4 + h] = s * 0.25f;
    }
    CP_WAIT_GROUP(0);
    __syncthreads();

    // ---- scores: thread = key row t, 4 heads ----
    float s0, s1, s2, s3;
    {
        const float4* krow = (const float4*)&ks[t * STRIDE];
        const float4* u4 = (const float4*)u;
        float a0 = 0.f, a1 = 0.f, a2 = 0.f, a3 = 0.f;
        #pragma unroll
        for (int c = 0; c < 16; c++) {
            float4 kv = krow[c];
            float4 ux = u4[4 * c + 0], uy = u4[4 * c + 1];
            float4 uz = u4[4 * c + 2], uw = u4[4 * c + 3];
            a0 += kv.x * ux.x + kv.y * uy.x + kv.z * uz.x + kv.w * uw.x;
            a1 += kv.x * ux.y + kv.y * uy.y + kv.z * uz.y + kv.w * uw.y;
            a2 += kv.x * ux.z + kv.y * uy.z + kv.z * uz.z + kv.w * uw.z;
            a3 += kv.x * ux.w + kv.y * uy.w + kv.z * uz.w + kv.w * uw.w;
        }
        bool masked = (kmv != 1) || ((k0 + t) == 0);
        s0 = masked ? NEGF : a0;
        s1 = masked ? NEGF : a1;
        s2 = masked ? NEGF : a2;
        s3 = masked ? NEGF : a3;
    }

    // block max per head (8 warps)
    {
        float m0 = s0, m1 = s1, m2 = s2, m3 = s3;
        #pragma unroll
        for (int o = 16; o; o >>= 1) {
            m0 = fmaxf(m0, __shfl_xor_sync(0xffffffffu, m0, o));
            m1 = fmaxf(m1, __shfl_xor_sync(0xffffffffu, m1, o));
            m2 = fmaxf(m2, __shfl_xor_sync(0xffffffffu, m2, o));
            m3 = fmaxf(m3, __shfl_xor_sync(0xffffffffu, m3, o));
        }
        if (lane == 0) {
            wred[wid * 4 + 0] = m0; wred[wid * 4 + 1] = m1;
            wred[wid * 4 + 2] = m2; wred[wid * 4 + 3] = m3;
        }
    }
    __syncthreads();
    if (t < 4) {
        float m = wred[t];
        #pragma unroll
        for (int w = 1; w < 8; w++) m = fmaxf(m, wred[w * 4 + t]);
        mh[t] = m;
    }
    __syncthreads();

    // p = exp(s - m); block sum per head
    {
        float p0 = __expf(s0 - mh[0]);
        float p1 = __expf(s1 - mh[1]);
        float p2 = __expf(s2 - mh[2]);
        float p3 = __expf(s3 - mh[3]);
        p4[t] = make_float4(p0, p1, p2, p3);
        float l0 = p0, l1 = p1, l2 = p2, l3 = p3;
        #pragma unroll
        for (int o = 16; o; o >>= 1) {
            l0 += __shfl_xor_sync(0xffffffffu, l0, o);
            l1 += __shfl_xor_sync(0xffffffffu, l1, o);
            l2 += __shfl_xor_sync(0xffffffffu, l2, o);
            l3 += __shfl_xor_sync(0xffffffffu, l3, o);
        }
        if (lane == 0) {
            wred[wid * 4 + 0] = l0; wred[wid * 4 + 1] = l1;
            wred[wid * 4 + 2] = l2; wred[wid * 4 + 3] = l3;
        }
    }
    __syncthreads();
    if (t < 4) {
        float l = wred[t];
        #pragma unroll
        for (int w = 1; w < 8; w++) l += wred[w * 4 + t];
        g_pm[b * 16 + r * 4 + t] = mh[t];
        g_pl[b * 16 + r * 4 + t] = l;
    }

    // weighted key sum: thread (d, quarter) over 64 rows
    {
        int d = t & 63, q = t >> 6;
        float ax = 0.f, ay = 0.f, az = 0.f, aw = 0.f;
        const int kb = q * 64;
        #pragma unroll 4
        for (int kk = 0; kk < 64; kk++) {
            float kv = ks[(kb + kk) * STRIDE + d];
            float4 p = p4[kb + kk];
            ax += p.x * kv; ay += p.y * kv; az += p.z * kv; aw += p.w * kv;
        }
        ((float4*)accf)[t] = make_float4(ax, ay, az, aw);
    }
    __syncthreads();
    if (t < 64) {
        float4* am = (float4*)accf;
        float4 a = am[t], c = am[64 + t], d4 = am[128 + t], e = am[192 + t];
        float* gp = g_pacc + (b * NRANK + r) * 256;
        gp[0 * 64 + t] = a.x + c.x + d4.x + e.x;
        gp[1 * 64 + t] = a.y + c.y + d4.y + e.y;
        gp[2 * 64 + t] = a.z + c.z + d4.z + e.z;
        gp[3 * 64 + t] = a.w + c.w + d4.w + e.w;
    }
    __syncthreads();

    // ---- FFN quarter-slice prefetch into dead key tile (before the barrier) ----
    {
        const float4* g1 = (const float4*)fw1;                   // row stride = 64 f4
        const float4* g2 = (const float4*)(fw2 + r * 64 * 64);   // 1024 f4 contiguous
        #pragma unroll
        for (int i = 0; i < 4; i++) {
            int idx = t + i * 256;
            int row = idx >> 4, c = idx & 15;
            CP_ASYNC16(sbase + (FO_FW1 + idx * 4) * 4, g1 + row * 64 + r * 16 + c);
        }
        #pragma unroll
        for (int i = 0; i < 4; i++) {
            int idx = t + i * 256;
            CP_ASYNC16(sbase + (FO_FW2 + idx * 4) * 4, g2 + idx);
        }
        if (t < 16) {
            CP_ASYNC16(sbase + (FO_FB1 + t * 4) * 4, ((const float4*)(fb1 + r * 64)) + t);
        } else if (t < 32) {
            CP_ASYNC16(sbase + (FO_FB2 + (t - 16) * 4) * 4, ((const float4*)fb2) + (t - 16));
        }
        CP_COMMIT();
    }

    // ---- the ONE sync: hardware cluster barrier ----
    __threadfence();
    asm volatile("barrier.cluster.arrive.aligned;" ::: "memory");
    asm volatile("barrier.cluster.wait.aligned;"   ::: "memory");

    // ---- combine (redundant per rank; partials are L2-broadcast) ----
    if (t < 16) { m_s[t] = g_pm[b * 16 + t]; l_s[t] = g_pl[b * 16 + t]; }
    __syncthreads();
    if (t < 16) {
        float m = m_s[t], lv = l_s[t];
        float M = m;
        M = fmaxf(M, __shfl_xor_sync(0x0000ffffu, M, 4));
        M = fmaxf(M, __shfl_xor_sync(0x0000ffffu, M, 8));
        float f = __expf(m - M);
        f_s[t] = f;
        float L = lv * f;
        L += __shfl_xor_sync(0x0000ffffu, L, 4);
        L += __shfl_xor_sync(0x0000ffffu, L, 8);
        if (t < 4) sc_s[t] = sm[OFF_QM] / L;
    }
    __syncthreads();

    float* s_sm   = sm + OFF_ACC;         // 256
    float* part_s = sm + OFF_ACC + 256;   // 256
    float* res_s  = sm + OFF_KS + FO_RES;
    float* hid_s  = sm + OFF_KS + FO_HID;
    float* fw1s   = sm + OFF_KS + FO_FW1;
    float* fw2s   = sm + OFF_KS + FO_FW2;

    // s_sm[h*64+d] = (sum_r pacc) * qm/L
    {
        int d = t & 63, h = t >> 6;
        float S = 0.f;
        #pragma unroll
        for (int s = 0; s < NRANK; s++)
            S += g_pacc[b * 1024 + s * 256 + h * 64 + d] * f_s[s * 4 + h];
        s_sm[h * 64 + d] = S * sc_s[h];
    }
    __syncthreads();

    // res[j] = s_sm[h(j)] @ W_V[:,j] + q0[j]   (W_V demand loads, L2-broadcast)
    {
        int j = t & 63, q = t >> 6;
        int h = j >> 4;
        float a = 0.f;
        #pragma unroll
        for (int d = q * 16; d < q * 16 + 16; d++) a += s_sm[h * 64 + d] * W_V[d * 64 + j];
        part_s[t] = a;
    }
    CP_WAIT_GROUP(0);   // FFN slices ready
    __syncthreads();
    if (t < 64) {
        float o = part_s[t] + part_s[64 + t] + part_s[128 + t] + part_s[192 + t];
        res_s[t] = o + q0[t];
    }
    __syncthreads();

    // hidden quarter (64 units): thread (m = t&63, jq = t>>6) -> 16 j each
    {
        int m = t & 63, jq = t >> 6;
        float a = 0.f;
        #pragma unroll
        for (int j = jq * 16; j < jq * 16 + 16; j++) a += res_s[j] * fw1s[j * 64 + m];
        part_s[t] = a;
    }
    __syncthreads();
    if (t < 64) {
        float a = part_s[t] + part_s[64 + t] + part_s[128 + t] + part_s[192 + t]
                + sm[OFF_KS + FO_FB1 + t];
        hid_s[t] = (a > 0.f) ? a : 0.2f * a;
    }
    __syncthreads();

    // output partial over this rank's 64 hidden units
    {
        int j = t & 63, mq = t >> 6;
        float a = 0.f;
        #pragma unroll
        for (int m2 = mq * 16; m2 < mq * 16 + 16; m2++) a += hid_s[m2] * fw2s[m2 * 64 + j];
        part_s[t] = a;
    }
    __syncthreads();
    if (t < 64) {
        float v = part_s[t] + part_s[64 + t] + part_s[128 + t] + part_s[192 + t];
        if (r == 0) v += res_s[t] + sm[OFF_KS + FO_FB2 + t];
        atomicAdd(&out[b * 64 + t], v);
    }
}

extern "C" void kernel_launch(void* const* d_in, const int* in_sizes, int n_in,
                              void* d_out, int out_size)
{
    const float* queries = (const float*)d_in[0];
    const float* keys    = (const float*)d_in[1];
    const int*   qmask   = (const int*)d_in[2];
    const int*   kmask   = (const int*)d_in[3];
    const float* W_Q     = (const float*)d_in[4];
    const float* W_K     = (const float*)d_in[5];
    const float* W_V     = (const float*)d_in[6];
    const float* fw1     = (const float*)d_in[7];
    const float* fw2     = (const float*)d_in[8];
    const float* fb1     = (const float*)d_in[9];
    const float* fb2     = (const float*)d_in[10];
    float* out = (float*)d_out;

    cudaFuncSetAttribute(fused_transformer_kernel,
                         cudaFuncAttributeMaxDynamicSharedMemorySize, SM_BYTES);

    fused_transformer_kernel<<<dim3(NRANK, BB), 256, SM_BYTES>>>(
        queries, keys, qmask, kmask, W_Q, W_K, W_V, fw1, fw2, fb1, fb2, out);
}